// round 13
// baseline (speedup 1.0000x reference)
#include <cuda_runtime.h>
#include <cuda_fp16.h>
#include <cstdint>

// ---------------- problem constants ----------------
#define BB 4
#define CC 256
#define HH 96
#define WW 320
#define HW (HH * WW)          // 30720
#define MT 64                 // queries per CTA
#define NCHUNK 4              // 4 chunks of 64 channels (4 ksteps)
#define NTH 256
#define RAD 4
#define NCH 36

// ---------------- vol layout (floats) ----------------
#define GUARD 80              // zero guard each side (covers all OOB windows)
#define VROW 484              // 80 + 320 + 84; multiple of 4 -> float4 alignment
#define VOL_BYTES (MT * VROW * 4)   // 123904

// ---------------- stage layout (bytes), per 4-kstep stage ----------------
#define BSTR 656              // B row stride: 328 halves (41*16B, conflict-free)
#define ASTR 176              // A row stride: 88 halves (11*16B)
#define OFF_B 0
#define OFF_AH (64 * BSTR)             // 41984
#define OFF_AL (OFF_AH + 64 * ASTR)    // 53248
#define STAGE_BYTES (OFF_AL + 64 * ASTR)   // 64512 (x2 stages = 129024)
#define KS_B (16 * BSTR)      // per-kstep offset in B plane (10496)
#define KS_A (16 * ASTR)      // per-kstep offset in A planes (2816)
#define SMEM_BYTES (2 * STAGE_BYTES)   // 129024 >= vol (123904), vol overlays

static __device__ __forceinline__ uint32_t smem_u32(const void* p) {
    uint32_t a;
    asm("{ .reg .u64 t; cvta.to.shared.u64 t, %1; cvt.u32.u64 %0, t; }" : "=r"(a) : "l"(p));
    return a;
}

static __device__ __forceinline__ void ldsm4t(uint32_t* r, uint32_t a) {
    asm volatile("ldmatrix.sync.aligned.m8n8.x4.trans.shared.b16 {%0,%1,%2,%3}, [%4];"
                 : "=r"(r[0]), "=r"(r[1]), "=r"(r[2]), "=r"(r[3]) : "r"(a));
}
static __device__ __forceinline__ void ldsm2t(uint32_t* r, uint32_t a) {
    asm volatile("ldmatrix.sync.aligned.m8n8.x2.trans.shared.b16 {%0,%1}, [%2];"
                 : "=r"(r[0]), "=r"(r[1]) : "r"(a));
}
static __device__ __forceinline__ void mma16816(float* d, const uint32_t* a, const uint32_t* b) {
    asm volatile("mma.sync.aligned.m16n8k16.row.col.f32.f16.f16.f32 "
                 "{%0,%1,%2,%3}, {%4,%5,%6,%7}, {%8,%9}, {%0,%1,%2,%3};"
                 : "+f"(d[0]), "+f"(d[1]), "+f"(d[2]), "+f"(d[3])
                 : "r"(a[0]), "r"(a[1]), "r"(a[2]), "r"(a[3]), "r"(b[0]), "r"(b[1]));
}

// B: float4 -> fp16x4 (RN), one STS.64.
static __device__ __forceinline__ void cvt_sts_b(uint32_t addr, float4 x) {
    uint32_t p0, p1;
    asm("cvt.rn.f16x2.f32 %0, %1, %2;" : "=r"(p0) : "f"(x.y), "f"(x.x));
    asm("cvt.rn.f16x2.f32 %0, %1, %2;" : "=r"(p1) : "f"(x.w), "f"(x.z));
    asm volatile("st.shared.v2.b32 [%0], {%1,%2};" :: "r"(addr), "r"(p0), "r"(p1) : "memory");
}

// A: float4 -> hi fp16 (RN) + lo fp16 (residual); two STS.64.
static __device__ __forceinline__ void cvt_sts_a(uint32_t hi_a, uint32_t lo_a, float4 x) {
    uint32_t hp0, hp1;
    asm("cvt.rn.f16x2.f32 %0, %1, %2;" : "=r"(hp0) : "f"(x.y), "f"(x.x));
    asm("cvt.rn.f16x2.f32 %0, %1, %2;" : "=r"(hp1) : "f"(x.w), "f"(x.z));
    __half2 h0 = *(__half2*)&hp0, h1 = *(__half2*)&hp1;
    float r0 = x.x - __low2float(h0),  r1 = x.y - __high2float(h0);
    float r2 = x.z - __low2float(h1),  r3 = x.w - __high2float(h1);
    uint32_t lp0, lp1;
    asm("cvt.rn.f16x2.f32 %0, %1, %2;" : "=r"(lp0) : "f"(r1), "f"(r0));
    asm("cvt.rn.f16x2.f32 %0, %1, %2;" : "=r"(lp1) : "f"(r3), "f"(r2));
    asm volatile("st.shared.v2.b32 [%0], {%1,%2};" :: "r"(hi_a), "r"(hp0), "r"(hp1) : "memory");
    asm volatile("st.shared.v2.b32 [%0], {%1,%2};" :: "r"(lo_a), "r"(lp0), "r"(lp1) : "memory");
}

__global__ void __launch_bounds__(NTH, 1)
corr_hmma_kernel(const float* __restrict__ fmap1, const float* __restrict__ fmap2,
                 const float* __restrict__ cents, float* __restrict__ out) {
    extern __shared__ char smem[];
    const uint32_t sb = smem_u32(smem);
    const int t = threadIdx.x, wid = t >> 5, lid = t & 31;
    const int q0 = blockIdx.x * MT, h = blockIdx.y, b = blockIdx.z;

    // ---- load mapping: thread -> (channel-in-kstep, float4 position) ----
    const int ch  = t >> 4;   // 0..15
    const int pos = t & 15;   // 0..15
    const float* Ag = fmap1 + ((size_t)b * CC + ch) * HW + (size_t)h * WW + q0 + 4 * pos;
    const float* Bg = fmap2 + ((size_t)b * CC + ch) * HW + (size_t)h * WW + 4 * pos;

    // ---- per-lane ldmatrix offsets ----
    const int r8 = lid & 7, tl = lid >> 3;
    const uint32_t laneA = (uint32_t)((r8 + 8 * (tl >> 1)) * ASTR + (tl & 1) * 16);
    const uint32_t laneB = (uint32_t)((r8 + 8 * (tl & 1)) * BSTR + (tl >> 1) * 16);
    const uint32_t nbase = (uint32_t)(80 * wid);  // n = 40*wid

    const uint32_t sts_ah = sb + OFF_AH + (uint32_t)(ch * ASTR + 8 * pos);
    const uint32_t sts_al = sb + OFF_AL + (uint32_t)(ch * ASTR + 8 * pos);
    const uint32_t sts_b  = sb + OFF_B  + (uint32_t)(ch * BSTR + 8 * pos);

    float acc[4][5][4];
#pragma unroll
    for (int i = 0; i < 4; ++i)
#pragma unroll
        for (int j = 0; j < 5; ++j)
#pragma unroll
            for (int k2 = 0; k2 < 4; ++k2) acc[i][j][k2] = 0.0f;

    // ---- prologue: chunk 0 (4 ksteps) -> stage 0; chunk 1 pair P0 -> regs ----
    float4 ra[2], rb[2][5];
#pragma unroll
    for (int pr = 0; pr < 2; ++pr) {        // pair pr covers ksteps (2pr, 2pr+1)
#pragma unroll
        for (int ks = 0; ks < 2; ++ks) {
            const int kk = 2 * pr + ks;
            const size_t o = (size_t)(16 * kk) * HW;
            ra[ks] = *(const float4*)(Ag + o);
#pragma unroll
            for (int j = 0; j < 5; ++j) rb[ks][j] = *(const float4*)(Bg + o + 64 * j);
            cvt_sts_a(sts_ah + (uint32_t)(kk * KS_A), sts_al + (uint32_t)(kk * KS_A), ra[ks]);
#pragma unroll
            for (int j = 0; j < 5; ++j)
                cvt_sts_b(sts_b + (uint32_t)(kk * KS_B) + 128u * j, rb[ks][j]);
        }
    }
    // chunk 1, pair P0 (ksteps 0,1 of chunk 1) -> regs
#pragma unroll
    for (int ks = 0; ks < 2; ++ks) {
        const size_t o = (size_t)(64 + 16 * ks) * HW;
        ra[ks] = *(const float4*)(Ag + o);
#pragma unroll
        for (int j = 0; j < 5; ++j) rb[ks][j] = *(const float4*)(Bg + o + 64 * j);
    }
    __syncthreads();

    // ---- mainloop: 4 ksteps per phase, one barrier per 160 MMAs ----
    for (int c = 0; c < NCHUNK; ++c) {
        const uint32_t cur = sb + (uint32_t)((c & 1) * STAGE_BYTES);
        const uint32_t nxtoff = (uint32_t)(((c + 1) & 1) * STAGE_BYTES);

#pragma unroll
        for (int kk = 0; kk < 4; ++kk) {
            // ---- frags for kstep kk ----
            uint32_t ah[4][4], al[4][4], bh[10];
            {
                const uint32_t abh = cur + OFF_AH + (uint32_t)(kk * KS_A) + laneA;
                const uint32_t abl = cur + OFF_AL + (uint32_t)(kk * KS_A) + laneA;
#pragma unroll
                for (int i = 0; i < 4; ++i) {
                    ldsm4t(ah[i], abh + 32u * i);
                    ldsm4t(al[i], abl + 32u * i);
                }
                const uint32_t bb = cur + OFF_B + (uint32_t)(kk * KS_B) + laneB + nbase;
                ldsm4t(bh + 0, bb); ldsm4t(bh + 4, bb + 32u); ldsm2t(bh + 8, bb + 64u);
            }

            // ---- staging interleaved at kk==1 and kk==3 ----
            if (kk == 1 && c + 1 < NCHUNK) {
                // stage pair P0 (ksteps 0,1 of chunk c+1); then LDG pair P1
#pragma unroll
                for (int ks = 0; ks < 2; ++ks) {
                    const uint32_t ko_a = nxtoff + (uint32_t)(ks * KS_A);
                    const uint32_t ko_b = nxtoff + (uint32_t)(ks * KS_B);
                    cvt_sts_a(sts_ah + ko_a, sts_al + ko_a, ra[ks]);
#pragma unroll
                    for (int j = 0; j < 5; ++j)
                        cvt_sts_b(sts_b + ko_b + 128u * j, rb[ks][j]);
                }
#pragma unroll
                for (int ks = 0; ks < 2; ++ks) {
                    const size_t o = (size_t)((c + 1) * 64 + 32 + 16 * ks) * HW;
                    ra[ks] = *(const float4*)(Ag + o);
#pragma unroll
                    for (int j = 0; j < 5; ++j)
                        rb[ks][j] = *(const float4*)(Bg + o + 64 * j);
                }
            }
            if (kk == 3 && c + 1 < NCHUNK) {
                // stage pair P1 (ksteps 2,3 of chunk c+1); then LDG P0 of chunk c+2
#pragma unroll
                for (int ks = 0; ks < 2; ++ks) {
                    const uint32_t ko_a = nxtoff + (uint32_t)((2 + ks) * KS_A);
                    const uint32_t ko_b = nxtoff + (uint32_t)((2 + ks) * KS_B);
                    cvt_sts_a(sts_ah + ko_a, sts_al + ko_a, ra[ks]);
#pragma unroll
                    for (int j = 0; j < 5; ++j)
                        cvt_sts_b(sts_b + ko_b + 128u * j, rb[ks][j]);
                }
                if (c + 2 < NCHUNK) {
#pragma unroll
                    for (int ks = 0; ks < 2; ++ks) {
                        const size_t o = (size_t)((c + 2) * 64 + 16 * ks) * HW;
                        ra[ks] = *(const float4*)(Ag + o);
#pragma unroll
                        for (int j = 0; j < 5; ++j)
                            rb[ks][j] = *(const float4*)(Bg + o + 64 * j);
                    }
                }
            }

            // ---- 40 MMAs for kstep kk ----
#pragma unroll
            for (int i = 0; i < 4; ++i)
#pragma unroll
                for (int j = 0; j < 5; ++j) {
                    mma16816(acc[i][j], ah[i], bh + 2 * j);
                    mma16816(acc[i][j], al[i], bh + 2 * j);
                }
        }

        __syncthreads();  // frags read + STS drained before buffer reuse
    }

    // ---- zero vol guards (stage smem is dead now) ----
    float* vol = (float*)smem;
    {
        const int row = t >> 2, part = t & 3;
        float4 z = make_float4(0.f, 0.f, 0.f, 0.f);
        float4* rp = (float4*)(vol + row * VROW);
#pragma unroll
        for (int i = 0; i < 5; ++i) rp[part + 4 * i] = z;        // left: 20 float4
#pragma unroll
        for (int i = 0; i < 6; ++i) {                             // right: 21 float4
            const int idx = 100 + part + 4 * i;
            if (idx < 121) rp[idx] = z;
        }
    }

    // ---- accumulators -> vol ----
    {
        const int mr = lid >> 2, nc0 = 2 * (lid & 3);
        const float s = 0.0625f;  // 1/sqrt(256)
#pragma unroll
        for (int i = 0; i < 4; ++i)
#pragma unroll
            for (int j = 0; j < 5; ++j) {
                const int q = 16 * i + mr, v = 40 * wid + 8 * j + nc0;
                *(float2*)&vol[q * VROW + GUARD + v] =
                    make_float2(acc[i][j][0] * s, acc[i][j][1] * s);
                *(float2*)&vol[(q + 8) * VROW + GUARD + v] =
                    make_float2(acc[i][j][2] * s, acc[i][j][3] * s);
            }
    }
    __syncthreads();

    // ---- pyramid sampling: thread = (q, level); 10 disjoint windows/thread ----
    {
        const int q = t & 63, lvl = t >> 6;  // lvl uniform per warp pair
        const float cent = cents[((size_t)b * HH + h) * WW + q0 + q];
        const float inv = 1.0f / (float)(1 << lvl);
        const float xl = cent * inv - (float)RAD;
        const float fl = floorf(xl);
        const int i0 = (int)fl;
        const float tt = xl - fl;
        const float* p = vol + q * VROW + GUARD + i0 * (1 << lvl);

        float S[10];
        if (lvl == 0) {
#pragma unroll
            for (int d = 0; d < 10; ++d) S[d] = p[d];
        } else if (lvl == 1) {
#pragma unroll
            for (int d = 0; d < 10; ++d) {
                float2 v = ((const float2*)p)[d];
                S[d] = v.x + v.y;
            }
        } else if (lvl == 2) {
#pragma unroll
            for (int d = 0; d < 10; ++d) {
                float4 v = ((const float4*)p)[d];
                S[d] = (v.x + v.y) + (v.z + v.w);
            }
        } else {
#pragma unroll
            for (int d = 0; d < 10; ++d) {
                float4 v0 = ((const float4*)p)[2 * d];
                float4 v1 = ((const float4*)p)[2 * d + 1];
                S[d] = ((v0.x + v0.y) + (v0.z + v0.w)) + ((v1.x + v1.y) + (v1.z + v1.w));
            }
        }

        float* ob = out + (((size_t)b * NCH + lvl * 9) * HH + h) * WW + q0 + q;
#pragma unroll
        for (int d = 0; d < 9; ++d)
            ob[(size_t)d * HW] = (S[d] * (1.0f - tt) + S[d + 1] * tt) * inv;
    }
}

extern "C" void kernel_launch(void* const* d_in, const int* in_sizes, int n_in,
                              void* d_out, int out_size) {
    const float* fmap1 = (const float*)d_in[0];
    const float* fmap2 = (const float*)d_in[1];
    const float* cents = (const float*)d_in[2];
    float* out = (float*)d_out;

    cudaFuncSetAttribute(corr_hmma_kernel,
                         cudaFuncAttributeMaxDynamicSharedMemorySize, SMEM_BYTES);

    dim3 grid(WW / MT, HH, BB);  // (5, 96, 4)
    corr_hmma_kernel<<<grid, NTH, SMEM_BYTES>>>(fmap1, fmap2, cents, out);
}

// round 14
// speedup vs baseline: 1.1449x; 1.1449x over previous
#include <cuda_runtime.h>
#include <cuda_fp16.h>
#include <cstdint>

// ---------------- problem constants ----------------
#define BB 4
#define CC 256
#define HH 96
#define WW 320
#define HW (HH * WW)          // 30720
#define MT 64                 // queries per CTA
#define NCHUNK 8              // 8 chunks of 32 channels (2 ksteps)
#define NTH 256
#define RAD 4
#define NCH 36

// ---------------- vol layout (floats) ----------------
#define GUARD 80              // zero guard each side (covers all OOB windows)
#define VROW 484              // 80 + 320 + 84; multiple of 4 -> float4 alignment
#define VOL_BYTES (MT * VROW * 4)   // 123904

// ---------------- stage layout (bytes), per 2-kstep stage ----------------
#define BSTR 656              // B row stride: 328 halves (41*16B, conflict-free)
#define ASTR 176              // A row stride: 88 halves (11*16B)
#define OFF_B 0
#define OFF_A (32 * BSTR)              // 20992
#define STAGE_BYTES (OFF_A + 32 * ASTR)    // 26624 (x2 stages = 53248)
#define KS_B (16 * BSTR)      // per-kstep offset in B plane (10496)
#define KS_A (16 * ASTR)      // per-kstep offset in A plane (2816)
#define SMEM_BYTES VOL_BYTES  // vol (123904) overlays both stages (53248)

static __device__ __forceinline__ uint32_t smem_u32(const void* p) {
    uint32_t a;
    asm("{ .reg .u64 t; cvta.to.shared.u64 t, %1; cvt.u32.u64 %0, t; }" : "=r"(a) : "l"(p));
    return a;
}

static __device__ __forceinline__ void ldsm4t(uint32_t* r, uint32_t a) {
    asm volatile("ldmatrix.sync.aligned.m8n8.x4.trans.shared.b16 {%0,%1,%2,%3}, [%4];"
                 : "=r"(r[0]), "=r"(r[1]), "=r"(r[2]), "=r"(r[3]) : "r"(a));
}
static __device__ __forceinline__ void ldsm2t(uint32_t* r, uint32_t a) {
    asm volatile("ldmatrix.sync.aligned.m8n8.x2.trans.shared.b16 {%0,%1}, [%2];"
                 : "=r"(r[0]), "=r"(r[1]) : "r"(a));
}
static __device__ __forceinline__ void mma16816(float* d, const uint32_t* a, const uint32_t* b) {
    asm volatile("mma.sync.aligned.m16n8k16.row.col.f32.f16.f16.f32 "
                 "{%0,%1,%2,%3}, {%4,%5,%6,%7}, {%8,%9}, {%0,%1,%2,%3};"
                 : "+f"(d[0]), "+f"(d[1]), "+f"(d[2]), "+f"(d[3])
                 : "r"(a[0]), "r"(a[1]), "r"(a[2]), "r"(a[3]), "r"(b[0]), "r"(b[1]));
}

// float4 -> fp16x4 (RN), one STS.64.
static __device__ __forceinline__ void cvt_sts4(uint32_t addr, float4 x) {
    uint32_t p0, p1;
    asm("cvt.rn.f16x2.f32 %0, %1, %2;" : "=r"(p0) : "f"(x.y), "f"(x.x));
    asm("cvt.rn.f16x2.f32 %0, %1, %2;" : "=r"(p1) : "f"(x.w), "f"(x.z));
    asm volatile("st.shared.v2.b32 [%0], {%1,%2};" :: "r"(addr), "r"(p0), "r"(p1) : "memory");
}

__global__ void __launch_bounds__(NTH, 1)
corr_hmma_kernel(const float* __restrict__ fmap1, const float* __restrict__ fmap2,
                 const float* __restrict__ cents, float* __restrict__ out) {
    extern __shared__ char smem[];
    const uint32_t sb = smem_u32(smem);
    const int t = threadIdx.x, wid = t >> 5, lid = t & 31;
    const int q0 = blockIdx.x * MT, h = blockIdx.y, b = blockIdx.z;

    // ---- load mapping: thread -> (channel-in-kstep, float4 position) ----
    const int ch  = t >> 4;   // 0..15
    const int pos = t & 15;   // 0..15
    const float* Ag = fmap1 + ((size_t)b * CC + ch) * HW + (size_t)h * WW + q0 + 4 * pos;
    const float* Bg = fmap2 + ((size_t)b * CC + ch) * HW + (size_t)h * WW + 4 * pos;

    // ---- per-lane ldmatrix offsets ----
    const int r8 = lid & 7, tl = lid >> 3;
    const uint32_t laneA = (uint32_t)((r8 + 8 * (tl >> 1)) * ASTR + (tl & 1) * 16);
    const uint32_t laneB = (uint32_t)((r8 + 8 * (tl & 1)) * BSTR + (tl >> 1) * 16);
    const uint32_t nbase = (uint32_t)(80 * wid);  // n = 40*wid

    const uint32_t sts_a = sb + OFF_A + (uint32_t)(ch * ASTR + 8 * pos);
    const uint32_t sts_b = sb + OFF_B + (uint32_t)(ch * BSTR + 8 * pos);

    float acc[4][5][4];
#pragma unroll
    for (int i = 0; i < 4; ++i)
#pragma unroll
        for (int j = 0; j < 5; ++j)
#pragma unroll
            for (int k2 = 0; k2 < 4; ++k2) acc[i][j][k2] = 0.0f;

    // ---- prologue: chunk 0 (both ksteps) -> stage 0; chunk 1 -> registers ----
    float4 ra[2], rb[2][5];
#pragma unroll
    for (int ks = 0; ks < 2; ++ks) {
        const size_t o = (size_t)(16 * ks) * HW;
        ra[ks] = *(const float4*)(Ag + o);
#pragma unroll
        for (int j = 0; j < 5; ++j) rb[ks][j] = *(const float4*)(Bg + o + 64 * j);
        cvt_sts4(sts_a + (uint32_t)(ks * KS_A), ra[ks]);
#pragma unroll
        for (int j = 0; j < 5; ++j)
            cvt_sts4(sts_b + (uint32_t)(ks * KS_B) + 128u * j, rb[ks][j]);
    }
#pragma unroll
    for (int ks = 0; ks < 2; ++ks) {
        const size_t o = (size_t)(32 + 16 * ks) * HW;
        ra[ks] = *(const float4*)(Ag + o);
#pragma unroll
        for (int j = 0; j < 5; ++j) rb[ks][j] = *(const float4*)(Bg + o + 64 * j);
    }
    __syncthreads();

    // ---- mainloop: 2 ksteps per phase, one barrier per 40 MMAs/warp ----
    for (int c = 0; c < NCHUNK; ++c) {
        const uint32_t cur = sb + (uint32_t)((c & 1) * STAGE_BYTES);
        const uint32_t nxtoff = (uint32_t)(((c + 1) & 1) * STAGE_BYTES);

        // ---- frags kstep 0 (exposed chain — once per phase) ----
        uint32_t a0[4][4], b0[10];
        {
            const uint32_t ab = cur + OFF_A + laneA;
#pragma unroll
            for (int i = 0; i < 4; ++i) ldsm4t(a0[i], ab + 32u * i);
            const uint32_t bb = cur + OFF_B + laneB + nbase;
            ldsm4t(b0 + 0, bb); ldsm4t(b0 + 4, bb + 32u); ldsm2t(b0 + 8, bb + 64u);
        }

        // ---- MMA kstep 0 (20/warp) ----
#pragma unroll
        for (int i = 0; i < 4; ++i)
#pragma unroll
            for (int j = 0; j < 5; ++j)
                mma16816(acc[i][j], a0[i], b0 + 2 * j);

        // ---- frags kstep 1 (issue while kstep-0 MMAs drain) ----
        uint32_t a1[4][4], b1[10];
        {
            const uint32_t ab = cur + OFF_A + (uint32_t)KS_A + laneA;
#pragma unroll
            for (int i = 0; i < 4; ++i) ldsm4t(a1[i], ab + 32u * i);
            const uint32_t bb = cur + OFF_B + (uint32_t)KS_B + laneB + nbase;
            ldsm4t(b1 + 0, bb); ldsm4t(b1 + 4, bb + 32u); ldsm2t(b1 + 8, bb + 64u);
        }

        // ---- stage chunk c+1 (both ksteps); refill regs with chunk c+2 ----
        if (c + 1 < NCHUNK) {
#pragma unroll
            for (int ks = 0; ks < 2; ++ks) {
                cvt_sts4(sts_a + nxtoff + (uint32_t)(ks * KS_A), ra[ks]);
#pragma unroll
                for (int j = 0; j < 5; ++j)
                    cvt_sts4(sts_b + nxtoff + (uint32_t)(ks * KS_B) + 128u * j, rb[ks][j]);
            }
            if (c + 2 < NCHUNK) {
#pragma unroll
                for (int ks = 0; ks < 2; ++ks) {
                    const size_t o = (size_t)((c + 2) * 32 + 16 * ks) * HW;
                    ra[ks] = *(const float4*)(Ag + o);
#pragma unroll
                    for (int j = 0; j < 5; ++j)
                        rb[ks][j] = *(const float4*)(Bg + o + 64 * j);
                }
            }
        }

        // ---- MMA kstep 1 (20/warp) ----
#pragma unroll
        for (int i = 0; i < 4; ++i)
#pragma unroll
            for (int j = 0; j < 5; ++j)
                mma16816(acc[i][j], a1[i], b1 + 2 * j);

        __syncthreads();  // frags read + STS drained before buffer reuse
    }

    // ---- zero vol guards (stage smem is dead now) ----
    float* vol = (float*)smem;
    {
        const int row = t >> 2, part = t & 3;
        float4 z = make_float4(0.f, 0.f, 0.f, 0.f);
        float4* rp = (float4*)(vol + row * VROW);
#pragma unroll
        for (int i = 0; i < 5; ++i) rp[part + 4 * i] = z;        // left: 20 float4
#pragma unroll
        for (int i = 0; i < 6; ++i) {                             // right: 21 float4
            const int idx = 100 + part + 4 * i;
            if (idx < 121) rp[idx] = z;
        }
    }

    // ---- accumulators -> vol ----
    {
        const int mr = lid >> 2, nc0 = 2 * (lid & 3);
        const float s = 0.0625f;  // 1/sqrt(256)
#pragma unroll
        for (int i = 0; i < 4; ++i)
#pragma unroll
            for (int j = 0; j < 5; ++j) {
                const int q = 16 * i + mr, v = 40 * wid + 8 * j + nc0;
                *(float2*)&vol[q * VROW + GUARD + v] =
                    make_float2(acc[i][j][0] * s, acc[i][j][1] * s);
                *(float2*)&vol[(q + 8) * VROW + GUARD + v] =
                    make_float2(acc[i][j][2] * s, acc[i][j][3] * s);
            }
    }
    __syncthreads();

    // ---- pyramid sampling: thread = (q, level); 10 disjoint windows/thread ----
    {
        const int q = t & 63, lvl = t >> 6;  // lvl uniform per warp pair
        const float cent = cents[((size_t)b * HH + h) * WW + q0 + q];
        const float inv = 1.0f / (float)(1 << lvl);
        const float xl = cent * inv - (float)RAD;
        const float fl = floorf(xl);
        const int i0 = (int)fl;
        const float tt = xl - fl;
        const float* p = vol + q * VROW + GUARD + i0 * (1 << lvl);

        float S[10];
        if (lvl == 0) {
#pragma unroll
            for (int d = 0; d < 10; ++d) S[d] = p[d];
        } else if (lvl == 1) {
#pragma unroll
            for (int d = 0; d < 10; ++d) {
                float2 v = ((const float2*)p)[d];
                S[d] = v.x + v.y;
            }
        } else if (lvl == 2) {
#pragma unroll
            for (int d = 0; d < 10; ++d) {
                float4 v = ((const float4*)p)[d];
                S[d] = (v.x + v.y) + (v.z + v.w);
            }
        } else {
#pragma unroll
            for (int d = 0; d < 10; ++d) {
                float4 v0 = ((const float4*)p)[2 * d];
                float4 v1 = ((const float4*)p)[2 * d + 1];
                S[d] = ((v0.x + v0.y) + (v0.z + v0.w)) + ((v1.x + v1.y) + (v1.z + v1.w));
            }
        }

        float* ob = out + (((size_t)b * NCH + lvl * 9) * HH + h) * WW + q0 + q;
#pragma unroll
        for (int d = 0; d < 9; ++d)
            ob[(size_t)d * HW] = (S[d] * (1.0f - tt) + S[d + 1] * tt) * inv;
    }
}

extern "C" void kernel_launch(void* const* d_in, const int* in_sizes, int n_in,
                              void* d_out, int out_size) {
    const float* fmap1 = (const float*)d_in[0];
    const float* fmap2 = (const float*)d_in[1];
    const float* cents = (const float*)d_in[2];
    float* out = (float*)d_out;

    cudaFuncSetAttribute(corr_hmma_kernel,
                         cudaFuncAttributeMaxDynamicSharedMemorySize, SMEM_BYTES);

    dim3 grid(WW / MT, HH, BB);  // (5, 96, 4)
    corr_hmma_kernel<<<grid, NTH, SMEM_BYTES>>>(fmap1, fmap2, cents, out);
}

// round 15
// speedup vs baseline: 1.1822x; 1.0325x over previous
#include <cuda_runtime.h>
#include <cuda_fp16.h>
#include <cstdint>

// ---------------- problem constants ----------------
#define BB 4
#define CC 256
#define HH 96
#define WW 320
#define HW (HH * WW)          // 30720
#define MT 64                 // queries per tile
#define NCHUNK 8              // 8 chunks of 32 channels (2 ksteps)
#define NTH 256
#define RAD 4
#define NCH 36
#define NTILES (5 * HH * BB)  // 1920

// ---------------- stage layout (bytes), per 2-kstep stage ----------------
#define BSTR 656              // B row stride: 328 halves (41*16B, conflict-free)
#define ASTR 176              // A row stride: 88 halves (11*16B)
#define OFF_B 0
#define OFF_A (32 * BSTR)              // 20992
#define STAGE_BYTES (OFF_A + 32 * ASTR)    // 26624 (x2 stages = 53248)
#define KS_B (16 * BSTR)      // per-kstep offset in B plane (10496)
#define KS_A (16 * ASTR)      // per-kstep offset in A plane (2816)

// ---------------- vol layout (floats), separate from stages ----------------
#define GUARD 80              // zero guard each side (covers all OOB windows)
#define VROW 484              // 80 + 320 + 84
#define VOL_OFF (2 * STAGE_BYTES)          // 53248 (128B aligned)
#define VOL_BYTES (MT * VROW * 4)          // 123904
#define SMEM_BYTES (VOL_OFF + VOL_BYTES)   // 177152

static __device__ __forceinline__ uint32_t smem_u32(const void* p) {
    uint32_t a;
    asm("{ .reg .u64 t; cvta.to.shared.u64 t, %1; cvt.u32.u64 %0, t; }" : "=r"(a) : "l"(p));
    return a;
}

static __device__ __forceinline__ void ldsm4t(uint32_t* r, uint32_t a) {
    asm volatile("ldmatrix.sync.aligned.m8n8.x4.trans.shared.b16 {%0,%1,%2,%3}, [%4];"
                 : "=r"(r[0]), "=r"(r[1]), "=r"(r[2]), "=r"(r[3]) : "r"(a));
}
static __device__ __forceinline__ void ldsm2t(uint32_t* r, uint32_t a) {
    asm volatile("ldmatrix.sync.aligned.m8n8.x2.trans.shared.b16 {%0,%1}, [%2];"
                 : "=r"(r[0]), "=r"(r[1]) : "r"(a));
}
static __device__ __forceinline__ void mma16816(float* d, const uint32_t* a, const uint32_t* b) {
    asm volatile("mma.sync.aligned.m16n8k16.row.col.f32.f16.f16.f32 "
                 "{%0,%1,%2,%3}, {%4,%5,%6,%7}, {%8,%9}, {%0,%1,%2,%3};"
                 : "+f"(d[0]), "+f"(d[1]), "+f"(d[2]), "+f"(d[3])
                 : "r"(a[0]), "r"(a[1]), "r"(a[2]), "r"(a[3]), "r"(b[0]), "r"(b[1]));
}

// float4 -> fp16x4 (RN), one STS.64.
static __device__ __forceinline__ void cvt_sts4(uint32_t addr, float4 x) {
    uint32_t p0, p1;
    asm("cvt.rn.f16x2.f32 %0, %1, %2;" : "=r"(p0) : "f"(x.y), "f"(x.x));
    asm("cvt.rn.f16x2.f32 %0, %1, %2;" : "=r"(p1) : "f"(x.w), "f"(x.z));
    asm volatile("st.shared.v2.b32 [%0], {%1,%2};" :: "r"(addr), "r"(p0), "r"(p1) : "memory");
}

__global__ void __launch_bounds__(NTH, 1)
corr_hmma_kernel(const float* __restrict__ fmap1, const float* __restrict__ fmap2,
                 const float* __restrict__ cents, float* __restrict__ out) {
    extern __shared__ char smem[];
    const uint32_t sb = smem_u32(smem);
    const int t = threadIdx.x, wid = t >> 5, lid = t & 31;

    // ---- fixed per-thread staging mapping ----
    const int ch  = t >> 4;   // 0..15 channel-in-kstep
    const int pos = t & 15;   // float4 position

    // ---- per-lane ldmatrix offsets ----
    const int r8 = lid & 7, tl = lid >> 3;
    const uint32_t laneA = (uint32_t)((r8 + 8 * (tl >> 1)) * ASTR + (tl & 1) * 16);
    const uint32_t laneB = (uint32_t)((r8 + 8 * (tl & 1)) * BSTR + (tl >> 1) * 16);
    const uint32_t nbase = (uint32_t)(80 * wid);  // n = 40*wid

    const uint32_t sts_a = sb + OFF_A + (uint32_t)(ch * ASTR + 8 * pos);
    const uint32_t sts_b = sb + OFF_B + (uint32_t)(ch * BSTR + 8 * pos);

    float* vol = (float*)(smem + VOL_OFF);

    // ---- zero vol guards once (persistent; tiles only overwrite the middle) ----
    {
        const int row = t >> 2, part = t & 3;
        float4 z = make_float4(0.f, 0.f, 0.f, 0.f);
        float4* rp = (float4*)(vol + row * VROW);
#pragma unroll
        for (int i = 0; i < 5; ++i) rp[part + 4 * i] = z;        // left: 20 float4
#pragma unroll
        for (int i = 0; i < 6; ++i) {                             // right: 21 float4
            const int idx = 100 + part + 4 * i;
            if (idx < 121) rp[idx] = z;
        }
    }

    int tile = blockIdx.x;
    if (tile >= NTILES) return;

    // ---- pointers for first tile + issue chunk-0 LDGs ----
    int qt = tile % 5, rm = tile / 5, hh = rm % HH, bb2 = rm / HH;
    int q0 = qt * MT;
    const float* Ag = fmap1 + ((size_t)bb2 * CC + ch) * HW + (size_t)hh * WW + q0 + 4 * pos;
    const float* Bg = fmap2 + ((size_t)bb2 * CC + ch) * HW + (size_t)hh * WW + 4 * pos;

    float4 ra[2], rb[2][5];
#pragma unroll
    for (int ks = 0; ks < 2; ++ks) {
        const size_t o = (size_t)(16 * ks) * HW;
        ra[ks] = *(const float4*)(Ag + o);
#pragma unroll
        for (int j = 0; j < 5; ++j) rb[ks][j] = *(const float4*)(Bg + o + 64 * j);
    }

    for (;;) {
        // ---- stage chunk 0 (from regs); LDG chunk 1 into regs ----
#pragma unroll
        for (int ks = 0; ks < 2; ++ks) {
            cvt_sts4(sts_a + (uint32_t)(ks * KS_A), ra[ks]);
#pragma unroll
            for (int j = 0; j < 5; ++j)
                cvt_sts4(sts_b + (uint32_t)(ks * KS_B) + 128u * j, rb[ks][j]);
        }
#pragma unroll
        for (int ks = 0; ks < 2; ++ks) {
            const size_t o = (size_t)(32 + 16 * ks) * HW;
            ra[ks] = *(const float4*)(Ag + o);
#pragma unroll
            for (int j = 0; j < 5; ++j) rb[ks][j] = *(const float4*)(Bg + o + 64 * j);
        }
        __syncthreads();

        float acc[4][5][4];
#pragma unroll
        for (int i = 0; i < 4; ++i)
#pragma unroll
            for (int j = 0; j < 5; ++j)
#pragma unroll
                for (int k2 = 0; k2 < 4; ++k2) acc[i][j][k2] = 0.0f;

        // ---- mainloop: 2 ksteps per phase ----
        for (int c = 0; c < NCHUNK; ++c) {
            const uint32_t cur = sb + (uint32_t)((c & 1) * STAGE_BYTES);
            const uint32_t nxtoff = (uint32_t)(((c + 1) & 1) * STAGE_BYTES);

            uint32_t a0[4][4], b0[10];
            {
                const uint32_t ab = cur + OFF_A + laneA;
#pragma unroll
                for (int i = 0; i < 4; ++i) ldsm4t(a0[i], ab + 32u * i);
                const uint32_t bbq = cur + OFF_B + laneB + nbase;
                ldsm4t(b0 + 0, bbq); ldsm4t(b0 + 4, bbq + 32u); ldsm2t(b0 + 8, bbq + 64u);
            }
#pragma unroll
            for (int i = 0; i < 4; ++i)
#pragma unroll
                for (int j = 0; j < 5; ++j)
                    mma16816(acc[i][j], a0[i], b0 + 2 * j);

            uint32_t a1[4][4], b1[10];
            {
                const uint32_t ab = cur + OFF_A + (uint32_t)KS_A + laneA;
#pragma unroll
                for (int i = 0; i < 4; ++i) ldsm4t(a1[i], ab + 32u * i);
                const uint32_t bbq = cur + OFF_B + (uint32_t)KS_B + laneB + nbase;
                ldsm4t(b1 + 0, bbq); ldsm4t(b1 + 4, bbq + 32u); ldsm2t(b1 + 8, bbq + 64u);
            }

            if (c + 1 < NCHUNK) {
#pragma unroll
                for (int ks = 0; ks < 2; ++ks) {
                    cvt_sts4(sts_a + nxtoff + (uint32_t)(ks * KS_A), ra[ks]);
#pragma unroll
                    for (int j = 0; j < 5; ++j)
                        cvt_sts4(sts_b + nxtoff + (uint32_t)(ks * KS_B) + 128u * j, rb[ks][j]);
                }
                if (c + 2 < NCHUNK) {
#pragma unroll
                    for (int ks = 0; ks < 2; ++ks) {
                        const size_t o = (size_t)((c + 2) * 32 + 16 * ks) * HW;
                        ra[ks] = *(const float4*)(Ag + o);
#pragma unroll
                        for (int j = 0; j < 5; ++j)
                            rb[ks][j] = *(const float4*)(Bg + o + 64 * j);
                    }
                }
            }

#pragma unroll
            for (int i = 0; i < 4; ++i)
#pragma unroll
                for (int j = 0; j < 5; ++j)
                    mma16816(acc[i][j], a1[i], b1 + 2 * j);

            __syncthreads();
        }

        // ---- issue next tile's chunk-0 LDGs (hidden under epilogue) ----
        const int ntile = tile + (int)gridDim.x;
        const bool have_next = (ntile < NTILES);
        const float *nAg = Ag, *nBg = Bg;
        int nq0 = q0, nhh = hh, nbb = bb2;
        if (have_next) {
            const int nqt = ntile % 5, nrm = ntile / 5;
            nhh = nrm % HH; nbb = nrm / HH; nq0 = nqt * MT;
            nAg = fmap1 + ((size_t)nbb * CC + ch) * HW + (size_t)nhh * WW + nq0 + 4 * pos;
            nBg = fmap2 + ((size_t)nbb * CC + ch) * HW + (size_t)nhh * WW + 4 * pos;
#pragma unroll
            for (int ks = 0; ks < 2; ++ks) {
                const size_t o = (size_t)(16 * ks) * HW;
                ra[ks] = *(const float4*)(nAg + o);
#pragma unroll
                for (int j = 0; j < 5; ++j) rb[ks][j] = *(const float4*)(nBg + o + 64 * j);
            }
        }

        // ---- accumulators -> vol ----
        {
            const int mr = lid >> 2, nc0 = 2 * (lid & 3);
            const float s = 0.0625f;  // 1/sqrt(256)
#pragma unroll
            for (int i = 0; i < 4; ++i)
#pragma unroll
                for (int j = 0; j < 5; ++j) {
                    const int q = 16 * i + mr, v = 40 * wid + 8 * j + nc0;
                    *(float2*)&vol[q * VROW + GUARD + v] =
                        make_float2(acc[i][j][0] * s, acc[i][j][1] * s);
                    *(float2*)&vol[(q + 8) * VROW + GUARD + v] =
                        make_float2(acc[i][j][2] * s, acc[i][j][3] * s);
                }
        }
        __syncthreads();

        // ---- pyramid sampling: thread = (q, level); 10 disjoint windows ----
        {
            const int q = t & 63, lvl = t >> 6;
            const float cent = cents[((size_t)bb2 * HH + hh) * WW + q0 + q];
            const float inv = 1.0f / (float)(1 << lvl);
            const float xl = cent * inv - (float)RAD;
            const float fl = floorf(xl);
            const int i0 = (int)fl;
            const float tt = xl - fl;
            const float* p = vol + q * VROW + GUARD + i0 * (1 << lvl);

            float S[10];
            if (lvl == 0) {
#pragma unroll
                for (int d = 0; d < 10; ++d) S[d] = p[d];
            } else if (lvl == 1) {
#pragma unroll
                for (int d = 0; d < 10; ++d) {
                    float2 v = ((const float2*)p)[d];
                    S[d] = v.x + v.y;
                }
            } else if (lvl == 2) {
#pragma unroll
                for (int d = 0; d < 10; ++d) {
                    float4 v = ((const float4*)p)[d];
                    S[d] = (v.x + v.y) + (v.z + v.w);
                }
            } else {
#pragma unroll
                for (int d = 0; d < 10; ++d) {
                    float4 v0 = ((const float4*)p)[2 * d];
                    float4 v1 = ((const float4*)p)[2 * d + 1];
                    S[d] = ((v0.x + v0.y) + (v0.z + v0.w)) + ((v1.x + v1.y) + (v1.z + v1.w));
                }
            }

            float* ob = out + (((size_t)bb2 * NCH + lvl * 9) * HH + hh) * WW + q0 + q;
#pragma unroll
            for (int d = 0; d < 9; ++d)
                ob[(size_t)d * HW] = (S[d] * (1.0f - tt) + S[d + 1] * tt) * inv;
        }

        if (!have_next) break;
        tile = ntile; Ag = nAg; Bg = nBg; q0 = nq0; hh = nhh; bb2 = nbb;
        // NOTE: vol reads (sampling) of this tile precede the next acc->vol write
        // by the 8 mainloop barriers; stage writes below conflict with nothing.
    }
}

extern "C" void kernel_launch(void* const* d_in, const int* in_sizes, int n_in,
                              void* d_out, int out_size) {
    const float* fmap1 = (const float*)d_in[0];
    const float* fmap2 = (const float*)d_in[1];
    const float* cents = (const float*)d_in[2];
    float* out = (float*)d_out;

    cudaFuncSetAttribute(corr_hmma_kernel,
                         cudaFuncAttributeMaxDynamicSharedMemorySize, SMEM_BYTES);

    int dev = 0, sms = 148;
    cudaGetDevice(&dev);
    cudaDeviceGetAttribute(&sms, cudaDevAttrMultiProcessorCount, dev);
    if (sms > NTILES) sms = NTILES;

    corr_hmma_kernel<<<sms, NTH, SMEM_BYTES>>>(fmap1, fmap2, cents, out);
}